// round 1
// baseline (speedup 1.0000x reference)
#include <cuda_runtime.h>
#include <cuda_bf16.h>

// Problem constants (fixed by reference):
//   bsv=1, nq=nv=1024, E=128, NUM_DEPTH=128, NUM_POINTS=4, H=W=32, cams=heads=levels=1
// Inputs (metadata order):
//   0 query[1024,128] 1 key[1024,128] 2 value[1024,128] 3 ref_3d[131072,2]
//   4 spatial_shapes[1,2] 5 W_off[128,1024] 6 b_off[1024] 7 W_attn[128,512]
//   8 b_attn[512] 9 W_v[128,128] 10 b_v[128] 11 W_o[128,128] 12 b_o[128]
// Output: float32 [1024,128]

#define NQ 1024
#define NV 1024
#define EMB 128
#define ND 128
#define NP 4

// Scratch (allocation-free: __device__ globals)
__device__ float g_val[NV * EMB];      // value @ W_v + b_v
__device__ float g_S[NQ * NV];         // key @ val^T
__device__ float g_off[NQ * 1024];     // query @ W_off + b_off
__device__ float g_aw[NQ * 512];       // query @ W_attn + b_attn (pre-softmax)
__device__ float g_M[NQ * ND];         // sampled + contracted, pre-output-proj

// ---------------------------------------------------------------------------
// Generic fp32 GEMM, K=128 fixed, M=1024 fixed. BM=BN=64, BK=64, 256 threads,
// 4x4 register micro-tile. NT: B is [N,128] (compute A @ B^T). Otherwise B is
// [128,N] row-major. Optional bias[N] and residual[M,N] epilogue.
// ---------------------------------------------------------------------------
template <bool NT, bool HAS_BIAS, bool HAS_RES>
__global__ __launch_bounds__(256)
void gemm128(const float* __restrict__ A, const float* __restrict__ B,
             const float* __restrict__ bias, const float* __restrict__ resid,
             float* __restrict__ C, int N)
{
    __shared__ float As[64][65];
    __shared__ float Bs[64][65];

    const int tid = threadIdx.x;
    const int tx = tid & 15;        // 0..15 -> N
    const int ty = tid >> 4;        // 0..15 -> M
    const int bm = blockIdx.y * 64;
    const int bn = blockIdx.x * 64;

    float acc[4][4];
#pragma unroll
    for (int i = 0; i < 4; i++)
#pragma unroll
        for (int j = 0; j < 4; j++) acc[i][j] = 0.0f;

#pragma unroll
    for (int kt = 0; kt < 128; kt += 64) {
#pragma unroll
        for (int l = 0; l < 16; l++) {
            int idx = tid + l * 256;
            int r = idx >> 6, c = idx & 63;
            As[r][c] = A[(bm + r) * 128 + kt + c];
            if (NT) {
                // B[N,128]: tile rows are N, cols are K (same layout as A)
                Bs[r][c] = B[(bn + r) * 128 + kt + c];
            } else {
                // B[128,N]: tile rows are K, cols are N
                Bs[r][c] = B[(kt + r) * N + bn + c];
            }
        }
        __syncthreads();

#pragma unroll
        for (int k = 0; k < 64; k++) {
            float a[4], b[4];
#pragma unroll
            for (int i = 0; i < 4; i++) a[i] = As[ty * 4 + i][k];
#pragma unroll
            for (int j = 0; j < 4; j++) b[j] = NT ? Bs[tx * 4 + j][k]
                                                  : Bs[k][tx * 4 + j];
#pragma unroll
            for (int i = 0; i < 4; i++)
#pragma unroll
                for (int j = 0; j < 4; j++)
                    acc[i][j] = fmaf(a[i], b[j], acc[i][j]);
        }
        __syncthreads();
    }

#pragma unroll
    for (int i = 0; i < 4; i++) {
        int m = bm + ty * 4 + i;
#pragma unroll
        for (int j = 0; j < 4; j++) {
            int n = bn + tx * 4 + j;
            float v = acc[i][j];
            if (HAS_BIAS) v += bias[n];
            if (HAS_RES)  v += resid[m * N + n];
            C[m * N + n] = v;
        }
    }
}

// ---------------------------------------------------------------------------
// Sampler: one block per query q (128 threads = one per depth d).
// S[q,:] (1024 floats) staged in shared memory; per-thread softmax over 4
// points; bilinear gather of scalars from the S row; writes M[q,d].
// ---------------------------------------------------------------------------
__global__ __launch_bounds__(128)
void sample_kernel(const float* __restrict__ S, const float* __restrict__ off,
                   const float* __restrict__ aw, const float* __restrict__ ref3d,
                   float* __restrict__ M)
{
    __shared__ float srow[NV];
    const int q = blockIdx.x;
    const int d = threadIdx.x;

    // stage S row (coalesced)
    const float4* Sv = reinterpret_cast<const float4*>(S + q * NV);
#pragma unroll
    for (int i = 0; i < 2; i++) {
        float4 v = Sv[d + i * 128];
        srow[(d + i * 128) * 4 + 0] = v.x;
        srow[(d + i * 128) * 4 + 1] = v.y;
        srow[(d + i * 128) * 4 + 2] = v.z;
        srow[(d + i * 128) * 4 + 3] = v.w;
    }
    // NOTE: the float4 store pattern above scatters; rewrite as direct copy:
    __syncthreads();
    // (overwrite with the simple correct copy — scatter above already correct:
    //  element (d+i*128)*4+c == linear float index of float4 lane c)

    // softmax over 4 points
    const float4 awv = *reinterpret_cast<const float4*>(aw + q * 512 + d * 4);
    float mx = fmaxf(fmaxf(awv.x, awv.y), fmaxf(awv.z, awv.w));
    float e0 = __expf(awv.x - mx), e1 = __expf(awv.y - mx);
    float e2 = __expf(awv.z - mx), e3 = __expf(awv.w - mx);
    float inv = 1.0f / (e0 + e1 + e2 + e3);
    float w[4] = { e0 * inv, e1 * inv, e2 * inv, e3 * inv };

    const int qe = q * ND + d;
    const float rx = ref3d[qe * 2 + 0] * 32.0f - 0.5f;
    const float ry = ref3d[qe * 2 + 1] * 32.0f - 0.5f;

    const float4 o0 = *reinterpret_cast<const float4*>(off + q * 1024 + d * 8);
    const float4 o1 = *reinterpret_cast<const float4*>(off + q * 1024 + d * 8 + 4);
    float ox[4] = { o0.x, o0.z, o1.x, o1.z };
    float oy[4] = { o0.y, o0.w, o1.y, o1.w };

    float acc = 0.0f;
#pragma unroll
    for (int p = 0; p < 4; p++) {
        float x = rx + ox[p];
        float y = ry + oy[p];
        float xf = floorf(x), yf = floorf(y);
        int ix0 = (int)xf, iy0 = (int)yf;
        float wx1 = x - xf, wy1 = y - yf;
        float wx0 = 1.0f - wx1, wy0 = 1.0f - wy1;

        float s = 0.0f;
#pragma unroll
        for (int c = 0; c < 4; c++) {
            int cx = ix0 + (c & 1);
            int cy = iy0 + (c >> 1);
            float wt = ((c & 1) ? wx1 : wx0) * ((c >> 1) ? wy1 : wy0);
            if (cx >= 0 && cx < 32 && cy >= 0 && cy < 32)
                s += wt * srow[cy * 32 + cx];
        }
        acc += w[p] * s;
    }
    M[qe] = acc * (1.0f / 128.0f);
}

// ---------------------------------------------------------------------------
extern "C" void kernel_launch(void* const* d_in, const int* in_sizes, int n_in,
                              void* d_out, int out_size)
{
    const float* query  = (const float*)d_in[0];
    const float* key    = (const float*)d_in[1];
    const float* value  = (const float*)d_in[2];
    const float* ref3d  = (const float*)d_in[3];
    // d_in[4] spatial_shapes: fixed [[32,32]], hardcoded
    const float* W_off  = (const float*)d_in[5];
    const float* b_off  = (const float*)d_in[6];
    const float* W_attn = (const float*)d_in[7];
    const float* b_attn = (const float*)d_in[8];
    const float* W_v    = (const float*)d_in[9];
    const float* b_v    = (const float*)d_in[10];
    const float* W_o    = (const float*)d_in[11];
    const float* b_o    = (const float*)d_in[12];
    float* out = (float*)d_out;

    float *p_val, *p_S, *p_off, *p_aw, *p_M;
    cudaGetSymbolAddress((void**)&p_val, g_val);
    cudaGetSymbolAddress((void**)&p_S,   g_S);
    cudaGetSymbolAddress((void**)&p_off, g_off);
    cudaGetSymbolAddress((void**)&p_aw,  g_aw);
    cudaGetSymbolAddress((void**)&p_M,   g_M);

    dim3 blk(256);
    // 1. val = value @ W_v + b_v           [1024 x 128]
    gemm128<false, true, false><<<dim3(2, 16), blk>>>(value, W_v, b_v, nullptr, p_val, 128);
    // 2. off = query @ W_off + b_off       [1024 x 1024]
    gemm128<false, true, false><<<dim3(16, 16), blk>>>(query, W_off, b_off, nullptr, p_off, 1024);
    // 3. aw = query @ W_attn + b_attn      [1024 x 512]
    gemm128<false, true, false><<<dim3(8, 16), blk>>>(query, W_attn, b_attn, nullptr, p_aw, 512);
    // 4. S = key @ val^T                   [1024 x 1024]
    gemm128<true, false, false><<<dim3(16, 16), blk>>>(key, p_val, nullptr, nullptr, p_S, 1024);
    // 5. sample -> M                       [1024 x 128]
    sample_kernel<<<1024, 128>>>(p_S, p_off, p_aw, ref3d, p_M);
    // 6. out = M @ W_o + b_o + query       [1024 x 128]
    gemm128<false, true, true><<<dim3(2, 16), blk>>>(p_M, W_o, b_o, query, out, 128);
}

// round 3
// speedup vs baseline: 1.6122x; 1.6122x over previous
#include <cuda_runtime.h>
#include <cuda_bf16.h>
#include <cstdint>

// Problem constants (fixed by reference):
//   bsv=1, nq=nv=1024, E=128, NUM_DEPTH=128, NUM_POINTS=4, H=W=32, cams=heads=levels=1
// Inputs (metadata order):
//   0 query[1024,128] 1 key[1024,128] 2 value[1024,128] 3 ref_3d[131072,2]
//   4 spatial_shapes[1,2] 5 W_off[128,1024] 6 b_off[1024] 7 W_attn[128,512]
//   8 b_attn[512] 9 W_v[128,128] 10 b_v[128] 11 W_o[128,128] 12 b_o[128]
// Output: float32 [1024,128]

#define NQ 1024
#define NV 1024
#define ND 128

// Scratch (allocation-free: __device__ globals)
__device__ float g_val[NV * 128];      // value @ W_v + b_v
__device__ float g_S[NQ * NV];         // key @ val^T
__device__ float g_off[NQ * 1024];     // query @ W_off + b_off
__device__ float g_aw[NQ * 512];       // query @ W_attn + b_attn (pre-softmax)
__device__ float g_M[NQ * ND];         // sampled + contracted, pre-output-proj

// ---------------------------------------------------------------------------
// tf32 helpers
// ---------------------------------------------------------------------------
__device__ __forceinline__ uint32_t f2tf32(float f) {
    uint32_t u;
    asm("cvt.rna.tf32.f32 %0, %1;" : "=r"(u) : "f"(f));
    return u;
}

__device__ __forceinline__ void mma_tf32(float c[4], const uint32_t a[4],
                                         const uint32_t b[2]) {
    asm volatile(
        "mma.sync.aligned.m16n8k8.row.col.f32.tf32.tf32.f32 "
        "{%0,%1,%2,%3}, {%4,%5,%6,%7}, {%8,%9}, {%0,%1,%2,%3};"
        : "+f"(c[0]), "+f"(c[1]), "+f"(c[2]), "+f"(c[3])
        : "r"(a[0]), "r"(a[1]), "r"(a[2]), "r"(a[3]), "r"(b[0]), "r"(b[1]));
}

// ---------------------------------------------------------------------------
// tf32 GEMM core. M fixed multiple of 64, K=128. BM=BN=64, 128 threads
// (4 warps, 2x2 warp grid, 32x32 warp tile). A[M,128] row-major fp32.
// NT: B is [N,128] (compute A @ B^T); else B is [128,N] row-major.
// Optional bias[N] and residual[M,N] epilogue. All fp32 in/out, tf32 compute.
//
// smem pads chosen for conflict-free fragment LDS:
//   As[m][k]   pad 40: frag addr = 40*m' + k' -> bank (8*grp + lk): distinct
//   Bs NT[n][k] pad 40: same pattern
//   Bs NN[k][n] pad 72: frag addr = 72*k' + n' -> bank (8*lk + grp): distinct
// ---------------------------------------------------------------------------
template <bool NT, bool HAS_BIAS, bool HAS_RES>
__device__ __forceinline__ void gemm_core(
    const float* __restrict__ A, const float* __restrict__ B,
    const float* __restrict__ bias, const float* __restrict__ resid,
    float* __restrict__ C, int N, int bm, int bn)
{
    __shared__ uint32_t As[64 * 40];
    __shared__ uint32_t Bs[64 * 40];   // NN uses 32*72 = 2304 <= 2560 words

    const int tid  = threadIdx.x;
    const int lane = tid & 31;
    const int warp = tid >> 5;
    const int wm   = warp >> 1;        // 0..1
    const int wn   = warp & 1;         // 0..1
    const int grp  = lane >> 2;        // 0..7
    const int lk   = lane & 3;         // 0..3

    float acc[2][4][4];
#pragma unroll
    for (int mi = 0; mi < 2; mi++)
#pragma unroll
        for (int ni = 0; ni < 4; ni++)
#pragma unroll
            for (int r = 0; r < 4; r++) acc[mi][ni][r] = 0.0f;

#pragma unroll
    for (int kt = 0; kt < 4; kt++) {            // BK = 32
        // ---- stage A tile [64m x 32k] -> As[m][k], tf32-rounded
#pragma unroll
        for (int l = 0; l < 4; l++) {
            int f = tid + l * 128;
            int m = f >> 3, k4 = f & 7;
            float4 v = *reinterpret_cast<const float4*>(
                A + (bm + m) * 128 + kt * 32 + k4 * 4);
            uint32_t* d = &As[m * 40 + k4 * 4];
            d[0] = f2tf32(v.x); d[1] = f2tf32(v.y);
            d[2] = f2tf32(v.z); d[3] = f2tf32(v.w);
        }
        // ---- stage B tile
        if (NT) {
#pragma unroll
            for (int l = 0; l < 4; l++) {
                int f = tid + l * 128;
                int n = f >> 3, k4 = f & 7;
                float4 v = *reinterpret_cast<const float4*>(
                    B + (bn + n) * 128 + kt * 32 + k4 * 4);
                uint32_t* d = &Bs[n * 40 + k4 * 4];
                d[0] = f2tf32(v.x); d[1] = f2tf32(v.y);
                d[2] = f2tf32(v.z); d[3] = f2tf32(v.w);
            }
        } else {
#pragma unroll
            for (int l = 0; l < 4; l++) {
                int f = tid + l * 128;
                int k = f >> 4, n4 = f & 15;
                float4 v = *reinterpret_cast<const float4*>(
                    B + (kt * 32 + k) * N + bn + n4 * 4);
                uint32_t* d = &Bs[k * 72 + n4 * 4];
                d[0] = f2tf32(v.x); d[1] = f2tf32(v.y);
                d[2] = f2tf32(v.z); d[3] = f2tf32(v.w);
            }
        }
        __syncthreads();

        // ---- 4 mma k-steps of 8
#pragma unroll
        for (int k8 = 0; k8 < 4; k8++) {
            const int kb = k8 * 8;
            uint32_t a[2][4], b[4][2];
#pragma unroll
            for (int mi = 0; mi < 2; mi++) {
                int mr = wm * 32 + mi * 16 + grp;
                a[mi][0] = As[mr * 40 + kb + lk];
                a[mi][1] = As[(mr + 8) * 40 + kb + lk];
                a[mi][2] = As[mr * 40 + kb + lk + 4];
                a[mi][3] = As[(mr + 8) * 40 + kb + lk + 4];
            }
#pragma unroll
            for (int ni = 0; ni < 4; ni++) {
                int nc = wn * 32 + ni * 8 + grp;
                if (NT) {
                    b[ni][0] = Bs[nc * 40 + kb + lk];
                    b[ni][1] = Bs[nc * 40 + kb + lk + 4];
                } else {
                    b[ni][0] = Bs[(kb + lk) * 72 + nc];
                    b[ni][1] = Bs[(kb + lk + 4) * 72 + nc];
                }
            }
#pragma unroll
            for (int mi = 0; mi < 2; mi++)
#pragma unroll
                for (int ni = 0; ni < 4; ni++)
                    mma_tf32(acc[mi][ni], a[mi], b[ni]);
        }
        __syncthreads();
    }

    // ---- epilogue: fp32 float2 stores, optional bias/residual
#pragma unroll
    for (int mi = 0; mi < 2; mi++) {
#pragma unroll
        for (int h = 0; h < 2; h++) {
            int row = bm + wm * 32 + mi * 16 + grp + h * 8;
#pragma unroll
            for (int ni = 0; ni < 4; ni++) {
                int col = bn + wn * 32 + ni * 8 + 2 * lk;
                float2 v;
                v.x = acc[mi][ni][h * 2 + 0];
                v.y = acc[mi][ni][h * 2 + 1];
                if (HAS_BIAS) { v.x += bias[col]; v.y += bias[col + 1]; }
                if (HAS_RES)  { v.x += resid[row * N + col];
                                v.y += resid[row * N + col + 1]; }
                *reinterpret_cast<float2*>(C + row * N + col) = v;
            }
        }
    }
}

template <bool NT, bool HAS_BIAS, bool HAS_RES>
__global__ __launch_bounds__(128)
void gemm_tf32(const float* __restrict__ A, const float* __restrict__ B,
               const float* __restrict__ bias, const float* __restrict__ resid,
               float* __restrict__ C, int N)
{
    gemm_core<NT, HAS_BIAS, HAS_RES>(A, B, bias, resid, C, N,
                                     blockIdx.y * 64, blockIdx.x * 64);
}

// Fused query projections: blocks x<16 -> off [1024x1024], x>=16 -> aw [1024x512]
__global__ __launch_bounds__(128)
void qproj_fused(const float* __restrict__ q,
                 const float* __restrict__ Woff, const float* __restrict__ boff,
                 const float* __restrict__ Wattn, const float* __restrict__ battn,
                 float* __restrict__ off, float* __restrict__ aw)
{
    const int bx = blockIdx.x;
    if (bx < 16)
        gemm_core<false, true, false>(q, Woff, boff, nullptr, off, 1024,
                                      blockIdx.y * 64, bx * 64);
    else
        gemm_core<false, true, false>(q, Wattn, battn, nullptr, aw, 512,
                                      blockIdx.y * 64, (bx - 16) * 64);
}

// ---------------------------------------------------------------------------
// Sampler: one block per query q (128 threads = one per depth d).
// S[q,:] (1024 floats) staged in shared memory; per-thread softmax over 4
// points; bilinear gather of scalars from the S row; writes M[q,d].
// ---------------------------------------------------------------------------
__global__ __launch_bounds__(128)
void sample_kernel(const float* __restrict__ S, const float* __restrict__ off,
                   const float* __restrict__ aw, const float* __restrict__ ref3d,
                   float* __restrict__ M)
{
    __shared__ float srow[NV];
    const int q = blockIdx.x;
    const int d = threadIdx.x;

    const float4* Sv = reinterpret_cast<const float4*>(S + q * NV);
#pragma unroll
    for (int i = 0; i < 2; i++) {
        float4 v = Sv[d + i * 128];
        srow[(d + i * 128) * 4 + 0] = v.x;
        srow[(d + i * 128) * 4 + 1] = v.y;
        srow[(d + i * 128) * 4 + 2] = v.z;
        srow[(d + i * 128) * 4 + 3] = v.w;
    }
    __syncthreads();

    const float4 awv = *reinterpret_cast<const float4*>(aw + q * 512 + d * 4);
    float mx = fmaxf(fmaxf(awv.x, awv.y), fmaxf(awv.z, awv.w));
    float e0 = __expf(awv.x - mx), e1 = __expf(awv.y - mx);
    float e2 = __expf(awv.z - mx), e3 = __expf(awv.w - mx);
    float inv = 1.0f / (e0 + e1 + e2 + e3);
    float w[4] = { e0 * inv, e1 * inv, e2 * inv, e3 * inv };

    const int qe = q * ND + d;
    const float rx = ref3d[qe * 2 + 0] * 32.0f - 0.5f;
    const float ry = ref3d[qe * 2 + 1] * 32.0f - 0.5f;

    const float4 o0 = *reinterpret_cast<const float4*>(off + q * 1024 + d * 8);
    const float4 o1 = *reinterpret_cast<const float4*>(off + q * 1024 + d * 8 + 4);
    float ox[4] = { o0.x, o0.z, o1.x, o1.z };
    float oy[4] = { o0.y, o0.w, o1.y, o1.w };

    float acc = 0.0f;
#pragma unroll
    for (int p = 0; p < 4; p++) {
        float x = rx + ox[p];
        float y = ry + oy[p];
        float xf = floorf(x), yf = floorf(y);
        int ix0 = (int)xf, iy0 = (int)yf;
        float wx1 = x - xf, wy1 = y - yf;
        float wx0 = 1.0f - wx1, wy0 = 1.0f - wy1;

        float s = 0.0f;
#pragma unroll
        for (int c = 0; c < 4; c++) {
            int cx = ix0 + (c & 1);
            int cy = iy0 + (c >> 1);
            float wt = ((c & 1) ? wx1 : wx0) * ((c >> 1) ? wy1 : wy0);
            if (cx >= 0 && cx < 32 && cy >= 0 && cy < 32)
                s += wt * srow[cy * 32 + cx];
        }
        acc += w[p] * s;
    }
    M[qe] = acc * (1.0f / 128.0f);
}

// ---------------------------------------------------------------------------
extern "C" void kernel_launch(void* const* d_in, const int* in_sizes, int n_in,
                              void* d_out, int out_size)
{
    const float* query  = (const float*)d_in[0];
    const float* key    = (const float*)d_in[1];
    const float* value  = (const float*)d_in[2];
    const float* ref3d  = (const float*)d_in[3];
    // d_in[4] spatial_shapes: fixed [[32,32]], hardcoded
    const float* W_off  = (const float*)d_in[5];
    const float* b_off  = (const float*)d_in[6];
    const float* W_attn = (const float*)d_in[7];
    const float* b_attn = (const float*)d_in[8];
    const float* W_v    = (const float*)d_in[9];
    const float* b_v    = (const float*)d_in[10];
    const float* W_o    = (const float*)d_in[11];
    const float* b_o    = (const float*)d_in[12];
    float* out = (float*)d_out;

    float *p_val, *p_S, *p_off, *p_aw, *p_M;
    cudaGetSymbolAddress((void**)&p_val, g_val);
    cudaGetSymbolAddress((void**)&p_S,   g_S);
    cudaGetSymbolAddress((void**)&p_off, g_off);
    cudaGetSymbolAddress((void**)&p_aw,  g_aw);
    cudaGetSymbolAddress((void**)&p_M,   g_M);

    // 1. val = value @ W_v + b_v                 [1024 x 128]
    gemm_tf32<false, true, false><<<dim3(2, 16), 128>>>(value, W_v, b_v, nullptr, p_val, 128);
    // 2. off = q @ W_off + b_off ; aw = q @ W_attn + b_attn   (fused)
    qproj_fused<<<dim3(24, 16), 128>>>(query, W_off, b_off, W_attn, b_attn, p_off, p_aw);
    // 3. S = key @ val^T                          [1024 x 1024]
    gemm_tf32<true, false, false><<<dim3(16, 16), 128>>>(key, p_val, nullptr, nullptr, p_S, 1024);
    // 4. sample -> M                              [1024 x 128]
    sample_kernel<<<1024, 128>>>(p_S, p_off, p_aw, ref3d, p_M);
    // 5. out = M @ W_o + b_o + query              [1024 x 128]
    gemm_tf32<false, true, true><<<dim3(2, 16), 128>>>(p_M, W_o, b_o, query, out, 128);
}

// round 4
// speedup vs baseline: 1.9073x; 1.1831x over previous
#include <cuda_runtime.h>
#include <cuda_bf16.h>
#include <cstdint>

// Problem constants (fixed by reference):
//   bsv=1, nq=nv=1024, E=128, NUM_DEPTH=128, NUM_POINTS=4, H=W=32, cams=heads=levels=1
// Inputs (metadata order):
//   0 query[1024,128] 1 key[1024,128] 2 value[1024,128] 3 ref_3d[131072,2]
//   4 spatial_shapes[1,2] 5 W_off[128,1024] 6 b_off[1024] 7 W_attn[128,512]
//   8 b_attn[512] 9 W_v[128,128] 10 b_v[128] 11 W_o[128,128] 12 b_o[128]
// Output: float32 [1024,128]

#define NQ 1024
#define NV 1024
#define ND 128

// Scratch (allocation-free: __device__ globals)
__device__ float g_val[NV * 128];      // value @ W_v + b_v
__device__ float g_S[NQ * NV];         // key @ val^T
__device__ float g_off[NQ * 1024];     // query @ W_off + b_off
__device__ float g_aw[NQ * 512];       // query @ W_attn + b_attn (pre-softmax)
__device__ float g_M[NQ * ND];         // sampled + contracted, pre-output-proj

// ---------------------------------------------------------------------------
// tf32 helpers
// ---------------------------------------------------------------------------
__device__ __forceinline__ uint32_t f2tf32(float f) {
    uint32_t u;
    asm("cvt.rna.tf32.f32 %0, %1;" : "=r"(u) : "f"(f));
    return u;
}

__device__ __forceinline__ void mma_tf32(float c[4], const uint32_t a[4],
                                         const uint32_t b[2]) {
    asm volatile(
        "mma.sync.aligned.m16n8k8.row.col.f32.tf32.tf32.f32 "
        "{%0,%1,%2,%3}, {%4,%5,%6,%7}, {%8,%9}, {%0,%1,%2,%3};"
        : "+f"(c[0]), "+f"(c[1]), "+f"(c[2]), "+f"(c[3])
        : "r"(a[0]), "r"(a[1]), "r"(a[2]), "r"(a[3]), "r"(b[0]), "r"(b[1]));
}

// ---------------------------------------------------------------------------
// tf32 GEMM core, FULL-K staging (K=128). BM=BN=64, 128 threads (4 warps,
// 2x2 warp grid, 32x32 warp tiles). Single __syncthreads, MLP=32 float4
// loads in flight per thread during staging, then 16 uninterrupted MMA
// k-steps. A[M,128] row-major fp32.
// NT: B is [N,128] (compute A @ B^T); else B is [128,N] row-major.
// Optional bias[N] and residual[M,N] epilogue. fp32 in/out, tf32 compute.
//
// smem pads (conflict-free fragment LDS):
//   As[m][k]    stride 132: frag bank = (132*grp + lk) % 32 = 4*grp+lk distinct
//   Bs NT[n][k] stride 132: same
//   Bs NN[k][n] stride 72:  frag bank = (8*lk + grp + c) % 32 distinct
// ---------------------------------------------------------------------------
#define ASZ (64 * 132)
#define BSZ (128 * 72)          // >= 64*132 too
#define GEMM_SMEM ((ASZ + BSZ) * 4)

template <bool NT, bool HAS_BIAS, bool HAS_RES>
__device__ __forceinline__ void gemm_core(
    const float* __restrict__ A, const float* __restrict__ B,
    const float* __restrict__ bias, const float* __restrict__ resid,
    float* __restrict__ C, int N, int bm, int bn)
{
    extern __shared__ uint32_t sm[];
    uint32_t* As = sm;
    uint32_t* Bs = sm + ASZ;

    const int tid  = threadIdx.x;
    const int lane = tid & 31;
    const int warp = tid >> 5;
    const int wm   = warp >> 1;        // 0..1
    const int wn   = warp & 1;         // 0..1
    const int grp  = lane >> 2;        // 0..7
    const int lk   = lane & 3;         // 0..3

    // ---- stage A [64m x 128k]: 2048 float4, 16 per thread
#pragma unroll
    for (int l = 0; l < 16; l++) {
        int f = tid + l * 128;
        int m = f >> 5, k4 = f & 31;
        float4 v = *reinterpret_cast<const float4*>(A + (bm + m) * 128 + k4 * 4);
        uint32_t* d = &As[m * 132 + k4 * 4];
        d[0] = f2tf32(v.x); d[1] = f2tf32(v.y);
        d[2] = f2tf32(v.z); d[3] = f2tf32(v.w);
    }
    // ---- stage B
    if (NT) {
#pragma unroll
        for (int l = 0; l < 16; l++) {
            int f = tid + l * 128;
            int n = f >> 5, k4 = f & 31;
            float4 v = *reinterpret_cast<const float4*>(B + (bn + n) * 128 + k4 * 4);
            uint32_t* d = &Bs[n * 132 + k4 * 4];
            d[0] = f2tf32(v.x); d[1] = f2tf32(v.y);
            d[2] = f2tf32(v.z); d[3] = f2tf32(v.w);
        }
    } else {
#pragma unroll
        for (int l = 0; l < 16; l++) {
            int f = tid + l * 128;
            int k = f >> 4, n4 = f & 15;
            float4 v = *reinterpret_cast<const float4*>(B + k * N + bn + n4 * 4);
            uint32_t* d = &Bs[k * 72 + n4 * 4];
            d[0] = f2tf32(v.x); d[1] = f2tf32(v.y);
            d[2] = f2tf32(v.z); d[3] = f2tf32(v.w);
        }
    }
    __syncthreads();

    float acc[2][4][4];
#pragma unroll
    for (int mi = 0; mi < 2; mi++)
#pragma unroll
        for (int ni = 0; ni < 4; ni++)
#pragma unroll
            for (int r = 0; r < 4; r++) acc[mi][ni][r] = 0.0f;

#pragma unroll
    for (int k8 = 0; k8 < 16; k8++) {
        const int kb = k8 * 8;
        uint32_t a[2][4], b[4][2];
#pragma unroll
        for (int mi = 0; mi < 2; mi++) {
            int mr = wm * 32 + mi * 16 + grp;
            a[mi][0] = As[mr * 132 + kb + lk];
            a[mi][1] = As[(mr + 8) * 132 + kb + lk];
            a[mi][2] = As[mr * 132 + kb + lk + 4];
            a[mi][3] = As[(mr + 8) * 132 + kb + lk + 4];
        }
#pragma unroll
        for (int ni = 0; ni < 4; ni++) {
            int nc = wn * 32 + ni * 8 + grp;
            if (NT) {
                b[ni][0] = Bs[nc * 132 + kb + lk];
                b[ni][1] = Bs[nc * 132 + kb + lk + 4];
            } else {
                b[ni][0] = Bs[(kb + lk) * 72 + nc];
                b[ni][1] = Bs[(kb + lk + 4) * 72 + nc];
            }
        }
#pragma unroll
        for (int mi = 0; mi < 2; mi++)
#pragma unroll
            for (int ni = 0; ni < 4; ni++)
                mma_tf32(acc[mi][ni], a[mi], b[ni]);
    }

    // ---- epilogue: fp32 float2 stores, optional bias/residual
#pragma unroll
    for (int mi = 0; mi < 2; mi++) {
#pragma unroll
        for (int h = 0; h < 2; h++) {
            int row = bm + wm * 32 + mi * 16 + grp + h * 8;
#pragma unroll
            for (int ni = 0; ni < 4; ni++) {
                int col = bn + wn * 32 + ni * 8 + 2 * lk;
                float2 v;
                v.x = acc[mi][ni][h * 2 + 0];
                v.y = acc[mi][ni][h * 2 + 1];
                if (HAS_BIAS) { v.x += bias[col]; v.y += bias[col + 1]; }
                if (HAS_RES)  { v.x += resid[row * N + col];
                                v.y += resid[row * N + col + 1]; }
                *reinterpret_cast<float2*>(C + row * N + col) = v;
            }
        }
    }
}

template <bool NT, bool HAS_BIAS, bool HAS_RES>
__global__ __launch_bounds__(128)
void gemm_tf32(const float* __restrict__ A, const float* __restrict__ B,
               const float* __restrict__ bias, const float* __restrict__ resid,
               float* __restrict__ C, int N)
{
    gemm_core<NT, HAS_BIAS, HAS_RES>(A, B, bias, resid, C, N,
                                     blockIdx.y * 64, blockIdx.x * 64);
}

// Fused query projections: blocks x<16 -> off [1024x1024], x>=16 -> aw [1024x512]
__global__ __launch_bounds__(128)
void qproj_fused(const float* __restrict__ q,
                 const float* __restrict__ Woff, const float* __restrict__ boff,
                 const float* __restrict__ Wattn, const float* __restrict__ battn,
                 float* __restrict__ off, float* __restrict__ aw)
{
    const int bx = blockIdx.x;
    if (bx < 16)
        gemm_core<false, true, false>(q, Woff, boff, nullptr, off, 1024,
                                      blockIdx.y * 64, bx * 64);
    else
        gemm_core<false, true, false>(q, Wattn, battn, nullptr, aw, 512,
                                      blockIdx.y * 64, (bx - 16) * 64);
}

// ---------------------------------------------------------------------------
// Sampler: one block per query q, 256 threads. Threads (half, d) with
// half = t>>7 handling points {0,1} or {2,3} of depth d = t&127.
// S[q,:] staged in smem; softmax over 4 points; bilinear scalar gathers.
// Halves combined through smem; writes M[q,d].
// ---------------------------------------------------------------------------
__global__ __launch_bounds__(256)
void sample_kernel(const float* __restrict__ S, const float* __restrict__ off,
                   const float* __restrict__ aw, const float* __restrict__ ref3d,
                   float* __restrict__ M)
{
    __shared__ float srow[NV];
    __shared__ float partial[256];
    const int q = blockIdx.x;
    const int t = threadIdx.x;
    const int half = t >> 7;
    const int d = t & 127;

    // stage S row: 256 threads x 1 float4
    reinterpret_cast<float4*>(srow)[t] =
        reinterpret_cast<const float4*>(S + q * NV)[t];

    // softmax over 4 points (both halves compute; each uses its 2 weights)
    const float4 awv = *reinterpret_cast<const float4*>(aw + q * 512 + d * 4);
    float mx = fmaxf(fmaxf(awv.x, awv.y), fmaxf(awv.z, awv.w));
    float e0 = __expf(awv.x - mx), e1 = __expf(awv.y - mx);
    float e2 = __expf(awv.z - mx), e3 = __expf(awv.w - mx);
    float inv = 1.0f / (e0 + e1 + e2 + e3);
    float w0 = (half ? e2 : e0) * inv;
    float w1 = (half ? e3 : e1) * inv;

    const int qe = q * ND + d;
    const float rx = ref3d[qe * 2 + 0] * 32.0f - 0.5f;
    const float ry = ref3d[qe * 2 + 1] * 32.0f - 0.5f;

    // offsets for this half's 2 points
    const float4 o = *reinterpret_cast<const float4*>(
        off + q * 1024 + d * 8 + half * 4);
    float ox[2] = { o.x, o.z };
    float oy[2] = { o.y, o.w };
    float wp[2] = { w0, w1 };

    __syncthreads();

    float acc = 0.0f;
#pragma unroll
    for (int p = 0; p < 2; p++) {
        float x = rx + ox[p];
        float y = ry + oy[p];
        float xf = floorf(x), yf = floorf(y);
        int ix0 = (int)xf, iy0 = (int)yf;
        float wx1 = x - xf, wy1 = y - yf;
        float wx0 = 1.0f - wx1, wy0 = 1.0f - wy1;

        float s = 0.0f;
#pragma unroll
        for (int c = 0; c < 4; c++) {
            int cx = ix0 + (c & 1);
            int cy = iy0 + (c >> 1);
            float wt = ((c & 1) ? wx1 : wx0) * ((c >> 1) ? wy1 : wy0);
            if (cx >= 0 && cx < 32 && cy >= 0 && cy < 32)
                s += wt * srow[cy * 32 + cx];
        }
        acc += wp[p] * s;
    }
    partial[t] = acc;
    __syncthreads();
    if (t < 128)
        M[qe] = (partial[t] + partial[t + 128]) * (1.0f / 128.0f);
}

// ---------------------------------------------------------------------------
extern "C" void kernel_launch(void* const* d_in, const int* in_sizes, int n_in,
                              void* d_out, int out_size)
{
    const float* query  = (const float*)d_in[0];
    const float* key    = (const float*)d_in[1];
    const float* value  = (const float*)d_in[2];
    const float* ref3d  = (const float*)d_in[3];
    // d_in[4] spatial_shapes: fixed [[32,32]], hardcoded
    const float* W_off  = (const float*)d_in[5];
    const float* b_off  = (const float*)d_in[6];
    const float* W_attn = (const float*)d_in[7];
    const float* b_attn = (const float*)d_in[8];
    const float* W_v    = (const float*)d_in[9];
    const float* b_v    = (const float*)d_in[10];
    const float* W_o    = (const float*)d_in[11];
    const float* b_o    = (const float*)d_in[12];
    float* out = (float*)d_out;

    float *p_val, *p_S, *p_off, *p_aw, *p_M;
    cudaGetSymbolAddress((void**)&p_val, g_val);
    cudaGetSymbolAddress((void**)&p_S,   g_S);
    cudaGetSymbolAddress((void**)&p_off, g_off);
    cudaGetSymbolAddress((void**)&p_aw,  g_aw);
    cudaGetSymbolAddress((void**)&p_M,   g_M);

    // Opt-in to >48KB dynamic smem (idempotent host-side state, capture-safe)
    cudaFuncSetAttribute(gemm_tf32<false, true, false>,
                         cudaFuncAttributeMaxDynamicSharedMemorySize, GEMM_SMEM);
    cudaFuncSetAttribute(gemm_tf32<true, false, false>,
                         cudaFuncAttributeMaxDynamicSharedMemorySize, GEMM_SMEM);
    cudaFuncSetAttribute(gemm_tf32<false, true, true>,
                         cudaFuncAttributeMaxDynamicSharedMemorySize, GEMM_SMEM);
    cudaFuncSetAttribute(qproj_fused,
                         cudaFuncAttributeMaxDynamicSharedMemorySize, GEMM_SMEM);

    // Fork capture: qproj on side stream, val->S on main stream, join before
    // sampler. Streams/events created once (host resources, no device memory).
    static cudaStream_t s1 = nullptr;
    static cudaEvent_t evFork = nullptr, evJoin = nullptr;
    if (s1 == nullptr) {
        cudaStreamCreateWithFlags(&s1, cudaStreamNonBlocking);
        cudaEventCreateWithFlags(&evFork, cudaEventDisableTiming);
        cudaEventCreateWithFlags(&evJoin, cudaEventDisableTiming);
    }

    cudaEventRecord(evFork, (cudaStream_t)0);
    cudaStreamWaitEvent(s1, evFork, 0);

    // branch 1 (s1): off = q @ W_off + b_off ; aw = q @ W_attn + b_attn
    qproj_fused<<<dim3(24, 16), 128, GEMM_SMEM, s1>>>(
        query, W_off, b_off, W_attn, b_attn, p_off, p_aw);
    cudaEventRecord(evJoin, s1);

    // branch 0 (main): val = value @ W_v + b_v ; S = key @ val^T
    gemm_tf32<false, true, false><<<dim3(2, 16), 128, GEMM_SMEM>>>(
        value, W_v, b_v, nullptr, p_val, 128);
    gemm_tf32<true, false, false><<<dim3(16, 16), 128, GEMM_SMEM>>>(
        key, p_val, nullptr, nullptr, p_S, 1024);

    cudaStreamWaitEvent((cudaStream_t)0, evJoin, 0);

    // sample -> M [1024 x 128]
    sample_kernel<<<1024, 256>>>(p_S, p_off, p_aw, ref3d, p_M);
    // out = M @ W_o + b_o + query [1024 x 128]
    gemm_tf32<false, true, true><<<dim3(2, 16), 128, GEMM_SMEM>>>(
        p_M, W_o, b_o, query, out, 128);
}

// round 5
// speedup vs baseline: 2.1421x; 1.1231x over previous
#include <cuda_runtime.h>
#include <cuda_fp16.h>
#include <cstdint>

// Problem constants (fixed by reference):
//   bsv=1, nq=nv=1024, E=128, NUM_DEPTH=128, NUM_POINTS=4, H=W=32, cams=heads=levels=1
// Inputs (metadata order):
//   0 query[1024,128] 1 key[1024,128] 2 value[1024,128] 3 ref_3d[131072,2]
//   4 spatial_shapes[1,2] 5 W_off[128,1024] 6 b_off[1024] 7 W_attn[128,512]
//   8 b_attn[512] 9 W_v[128,128] 10 b_v[128] 11 W_o[128,128] 12 b_o[128]
// Output: float32 [1024,128]

#define NQ 1024
#define NV 1024
#define ND 128

// Scratch (allocation-free: __device__ globals)
__device__ float  g_val[NV * 128];     // value @ W_v + b_v           (fp32)
__device__ __half g_S[NQ * NV];        // key @ val^T                 (fp16)
__device__ __half g_off[NQ * 1024];    // query @ W_off + b_off       (fp16)
__device__ __half g_aw[NQ * 512];      // query @ W_attn + b_attn     (fp16)

// ---------------------------------------------------------------------------
// tf32 helpers
// ---------------------------------------------------------------------------
__device__ __forceinline__ uint32_t f2tf32(float f) {
    uint32_t u;
    asm("cvt.rna.tf32.f32 %0, %1;" : "=r"(u) : "f"(f));
    return u;
}

__device__ __forceinline__ void mma_tf32(float c[4], const uint32_t a[4],
                                         const uint32_t b[2]) {
    asm volatile(
        "mma.sync.aligned.m16n8k8.row.col.f32.tf32.tf32.f32 "
        "{%0,%1,%2,%3}, {%4,%5,%6,%7}, {%8,%9}, {%0,%1,%2,%3};"
        : "+f"(c[0]), "+f"(c[1]), "+f"(c[2]), "+f"(c[3])
        : "r"(a[0]), "r"(a[1]), "r"(a[2]), "r"(a[3]), "r"(b[0]), "r"(b[1]));
}

// ---------------------------------------------------------------------------
// tf32 GEMM core, FULL-K staging (K=128). BM=BN=64, 128 threads (4 warps,
// 2x2 warp grid, 32x32 warp tiles). Single __syncthreads, then 16
// uninterrupted MMA k-steps. A[M,128] row-major fp32.
// NT: B is [N,128] (compute A @ B^T); else B is [128,N] row-major.
// OUT_HALF: C is fp16 (half2 stores); else fp32. Optional bias[N].
// ---------------------------------------------------------------------------
#define ASZ (64 * 132)
#define BSZ (128 * 72)
#define GEMM_SMEM ((ASZ + BSZ) * 4)

template <bool NT, bool HAS_BIAS, bool OUT_HALF>
__device__ __forceinline__ void gemm_core(
    const float* __restrict__ A, const float* __restrict__ B,
    const float* __restrict__ bias, void* __restrict__ Cv,
    int N, int bm, int bn)
{
    extern __shared__ uint32_t sm[];
    uint32_t* As = sm;
    uint32_t* Bs = sm + ASZ;

    const int tid  = threadIdx.x;
    const int lane = tid & 31;
    const int warp = tid >> 5;
    const int wm   = warp >> 1;
    const int wn   = warp & 1;
    const int grp  = lane >> 2;
    const int lk   = lane & 3;

    // ---- stage A [64m x 128k]
#pragma unroll
    for (int l = 0; l < 16; l++) {
        int f = tid + l * 128;
        int m = f >> 5, k4 = f & 31;
        float4 v = *reinterpret_cast<const float4*>(A + (bm + m) * 128 + k4 * 4);
        uint32_t* d = &As[m * 132 + k4 * 4];
        d[0] = f2tf32(v.x); d[1] = f2tf32(v.y);
        d[2] = f2tf32(v.z); d[3] = f2tf32(v.w);
    }
    // ---- stage B
    if (NT) {
#pragma unroll
        for (int l = 0; l < 16; l++) {
            int f = tid + l * 128;
            int n = f >> 5, k4 = f & 31;
            float4 v = *reinterpret_cast<const float4*>(B + (bn + n) * 128 + k4 * 4);
            uint32_t* d = &Bs[n * 132 + k4 * 4];
            d[0] = f2tf32(v.x); d[1] = f2tf32(v.y);
            d[2] = f2tf32(v.z); d[3] = f2tf32(v.w);
        }
    } else {
#pragma unroll
        for (int l = 0; l < 16; l++) {
            int f = tid + l * 128;
            int k = f >> 4, n4 = f & 15;
            float4 v = *reinterpret_cast<const float4*>(B + k * N + bn + n4 * 4);
            uint32_t* d = &Bs[k * 72 + n4 * 4];
            d[0] = f2tf32(v.x); d[1] = f2tf32(v.y);
            d[2] = f2tf32(v.z); d[3] = f2tf32(v.w);
        }
    }
    __syncthreads();

    float acc[2][4][4];
#pragma unroll
    for (int mi = 0; mi < 2; mi++)
#pragma unroll
        for (int ni = 0; ni < 4; ni++)
#pragma unroll
            for (int r = 0; r < 4; r++) acc[mi][ni][r] = 0.0f;

#pragma unroll
    for (int k8 = 0; k8 < 16; k8++) {
        const int kb = k8 * 8;
        uint32_t a[2][4], b[4][2];
#pragma unroll
        for (int mi = 0; mi < 2; mi++) {
            int mr = wm * 32 + mi * 16 + grp;
            a[mi][0] = As[mr * 132 + kb + lk];
            a[mi][1] = As[(mr + 8) * 132 + kb + lk];
            a[mi][2] = As[mr * 132 + kb + lk + 4];
            a[mi][3] = As[(mr + 8) * 132 + kb + lk + 4];
        }
#pragma unroll
        for (int ni = 0; ni < 4; ni++) {
            int nc = wn * 32 + ni * 8 + grp;
            if (NT) {
                b[ni][0] = Bs[nc * 132 + kb + lk];
                b[ni][1] = Bs[nc * 132 + kb + lk + 4];
            } else {
                b[ni][0] = Bs[(kb + lk) * 72 + nc];
                b[ni][1] = Bs[(kb + lk + 4) * 72 + nc];
            }
        }
#pragma unroll
        for (int mi = 0; mi < 2; mi++)
#pragma unroll
            for (int ni = 0; ni < 4; ni++)
                mma_tf32(acc[mi][ni], a[mi], b[ni]);
    }

    // ---- epilogue
#pragma unroll
    for (int mi = 0; mi < 2; mi++) {
#pragma unroll
        for (int h = 0; h < 2; h++) {
            int row = bm + wm * 32 + mi * 16 + grp + h * 8;
#pragma unroll
            for (int ni = 0; ni < 4; ni++) {
                int col = bn + wn * 32 + ni * 8 + 2 * lk;
                float vx = acc[mi][ni][h * 2 + 0];
                float vy = acc[mi][ni][h * 2 + 1];
                if (HAS_BIAS) { vx += bias[col]; vy += bias[col + 1]; }
                if (OUT_HALF) {
                    __half2 hv = __floats2half2_rn(vx, vy);
                    *reinterpret_cast<__half2*>(
                        (__half*)Cv + (size_t)row * N + col) = hv;
                } else {
                    float2 v2; v2.x = vx; v2.y = vy;
                    *reinterpret_cast<float2*>(
                        (float*)Cv + (size_t)row * N + col) = v2;
                }
            }
        }
    }
}

template <bool NT, bool HAS_BIAS, bool OUT_HALF>
__global__ __launch_bounds__(128)
void gemm_tf32(const float* __restrict__ A, const float* __restrict__ B,
               const float* __restrict__ bias, void* __restrict__ C, int N)
{
    gemm_core<NT, HAS_BIAS, OUT_HALF>(A, B, bias, C, N,
                                      blockIdx.y * 64, blockIdx.x * 64);
}

// Fused query projections: blocks x<16 -> off [1024x1024], x>=16 -> aw [1024x512]
__global__ __launch_bounds__(128)
void qproj_fused(const float* __restrict__ q,
                 const float* __restrict__ Woff, const float* __restrict__ boff,
                 const float* __restrict__ Wattn, const float* __restrict__ battn,
                 __half* __restrict__ off, __half* __restrict__ aw)
{
    const int bx = blockIdx.x;
    if (bx < 16)
        gemm_core<false, true, true>(q, Woff, boff, off, 1024,
                                     blockIdx.y * 64, bx * 64);
    else
        gemm_core<false, true, true>(q, Wattn, battn, aw, 512,
                                     blockIdx.y * 64, (bx - 16) * 64);
}

// ---------------------------------------------------------------------------
// Fused sampler + output projection. One block per query q, 256 threads.
// Phase 1: threads (half,d) sample 2 points each of depth d from the fp16
//          S row staged in smem; reduce halves -> M[q,0:128] in smem.
// Phase 2: out[q,e] = query[q,e] + b_o[e] + sum_d M[d]*W_o[d,e], with the
//          d-range split across the two halves (coalesced W_o rows).
// ---------------------------------------------------------------------------
__global__ __launch_bounds__(256)
void sample_out_kernel(const __half* __restrict__ S,
                       const __half* __restrict__ off,
                       const __half* __restrict__ aw,
                       const float* __restrict__ ref3d,
                       const float* __restrict__ W_o,
                       const float* __restrict__ b_o,
                       const float* __restrict__ query,
                       float* __restrict__ out)
{
    __shared__ __half srow[NV];
    __shared__ float red[256];
    __shared__ float Ms[ND];
    const int q = blockIdx.x;
    const int t = threadIdx.x;
    const int hf = t >> 7;
    const int d = t & 127;

    // stage S row: 1024 halves = 2KB; 256 threads x uint2 (4 halves)
    reinterpret_cast<uint2*>(srow)[t] =
        reinterpret_cast<const uint2*>(S + (size_t)q * NV)[t];

    // softmax over 4 points (fp16 logits)
    const __half2* awp = reinterpret_cast<const __half2*>(aw + q * 512 + d * 4);
    float2 a01 = __half22float2(awp[0]);
    float2 a23 = __half22float2(awp[1]);
    float mx = fmaxf(fmaxf(a01.x, a01.y), fmaxf(a23.x, a23.y));
    float e0 = __expf(a01.x - mx), e1 = __expf(a01.y - mx);
    float e2 = __expf(a23.x - mx), e3 = __expf(a23.y - mx);
    float inv = 1.0f / (e0 + e1 + e2 + e3);
    float wp[2] = { (hf ? e2 : e0) * inv, (hf ? e3 : e1) * inv };

    const int qe = q * ND + d;
    const float2 rf = *reinterpret_cast<const float2*>(ref3d + qe * 2);
    const float rx = rf.x * 32.0f - 0.5f;
    const float ry = rf.y * 32.0f - 0.5f;

    // offsets for this half's 2 points: (x0,y0),(x1,y1)
    const __half2* op = reinterpret_cast<const __half2*>(
        off + q * 1024 + d * 8 + hf * 4);
    float2 p0 = __half22float2(op[0]);
    float2 p1 = __half22float2(op[1]);
    float ox[2] = { p0.x, p1.x };
    float oy[2] = { p0.y, p1.y };

    __syncthreads();

    float acc = 0.0f;
#pragma unroll
    for (int p = 0; p < 2; p++) {
        float x = rx + ox[p];
        float y = ry + oy[p];
        float xf = floorf(x), yf = floorf(y);
        int ix0 = (int)xf, iy0 = (int)yf;
        float wx1 = x - xf, wy1 = y - yf;
        float wx0 = 1.0f - wx1, wy0 = 1.0f - wy1;

        float s = 0.0f;
#pragma unroll
        for (int c = 0; c < 4; c++) {
            int cx = ix0 + (c & 1);
            int cy = iy0 + (c >> 1);
            float wt = ((c & 1) ? wx1 : wx0) * ((c >> 1) ? wy1 : wy0);
            if (cx >= 0 && cx < 32 && cy >= 0 && cy < 32)
                s += wt * __half2float(srow[cy * 32 + cx]);
        }
        acc += wp[p] * s;
    }
    red[t] = acc;
    __syncthreads();
    if (t < 128) Ms[t] = (red[t] + red[t + 128]) * (1.0f / 128.0f);
    __syncthreads();

    // output projection: this half covers d-range [hf*64, hf*64+64)
    float acc2 = 0.0f;
    const int d0 = hf * 64;
#pragma unroll 8
    for (int dd = 0; dd < 64; dd++)
        acc2 = fmaf(Ms[d0 + dd], W_o[(d0 + dd) * 128 + d], acc2);
    red[t] = acc2;
    __syncthreads();
    if (t < 128)
        out[qe] = red[t] + red[t + 128] + b_o[t] + query[qe];
}

// ---------------------------------------------------------------------------
extern "C" void kernel_launch(void* const* d_in, const int* in_sizes, int n_in,
                              void* d_out, int out_size)
{
    const float* query  = (const float*)d_in[0];
    const float* key    = (const float*)d_in[1];
    const float* value  = (const float*)d_in[2];
    const float* ref3d  = (const float*)d_in[3];
    // d_in[4] spatial_shapes: fixed [[32,32]], hardcoded
    const float* W_off  = (const float*)d_in[5];
    const float* b_off  = (const float*)d_in[6];
    const float* W_attn = (const float*)d_in[7];
    const float* b_attn = (const float*)d_in[8];
    const float* W_v    = (const float*)d_in[9];
    const float* b_v    = (const float*)d_in[10];
    const float* W_o    = (const float*)d_in[11];
    const float* b_o    = (const float*)d_in[12];
    float* out = (float*)d_out;

    float *p_val;
    __half *p_S, *p_off, *p_aw;
    cudaGetSymbolAddress((void**)&p_val, g_val);
    cudaGetSymbolAddress((void**)&p_S,   g_S);
    cudaGetSymbolAddress((void**)&p_off, g_off);
    cudaGetSymbolAddress((void**)&p_aw,  g_aw);

    cudaFuncSetAttribute(gemm_tf32<false, true, false>,
                         cudaFuncAttributeMaxDynamicSharedMemorySize, GEMM_SMEM);
    cudaFuncSetAttribute(gemm_tf32<true, false, true>,
                         cudaFuncAttributeMaxDynamicSharedMemorySize, GEMM_SMEM);
    cudaFuncSetAttribute(qproj_fused,
                         cudaFuncAttributeMaxDynamicSharedMemorySize, GEMM_SMEM);

    // Fork capture: qproj on side stream; val->S on main stream; join before
    // fused sampler. Streams/events created once (host resources only).
    static cudaStream_t s1 = nullptr;
    static cudaEvent_t evFork = nullptr, evJoin = nullptr;
    if (s1 == nullptr) {
        cudaStreamCreateWithFlags(&s1, cudaStreamNonBlocking);
        cudaEventCreateWithFlags(&evFork, cudaEventDisableTiming);
        cudaEventCreateWithFlags(&evJoin, cudaEventDisableTiming);
    }

    cudaEventRecord(evFork, (cudaStream_t)0);
    cudaStreamWaitEvent(s1, evFork, 0);

    // branch 1 (s1): off/aw projections (fp16 outputs)
    qproj_fused<<<dim3(24, 16), 128, GEMM_SMEM, s1>>>(
        query, W_off, b_off, W_attn, b_attn, p_off, p_aw);
    cudaEventRecord(evJoin, s1);

    // branch 0: val = value @ W_v + b_v (fp32), then S = key @ val^T (fp16)
    gemm_tf32<false, true, false><<<dim3(2, 16), 128, GEMM_SMEM>>>(
        value, W_v, b_v, p_val, 128);
    gemm_tf32<true, false, true><<<dim3(16, 16), 128, GEMM_SMEM>>>(
        key, p_val, nullptr, p_S, 1024);

    cudaStreamWaitEvent((cudaStream_t)0, evJoin, 0);

    // fused sampler + output projection + residual
    sample_out_kernel<<<1024, 256>>>(p_S, p_off, p_aw, ref3d,
                                     W_o, b_o, query, out);
}